// round 9
// baseline (speedup 1.0000x reference)
#include <cuda_runtime.h>
#include <cuda_bf16.h>
#include <stdint.h>

#define NN   8192
#define DIN  512
#define DOUT 512

// ---------------------------------------------------------------------------
// Device scratch (static __device__ globals; allocation-free rule)
// ---------------------------------------------------------------------------
__device__ __nv_bfloat16 g_x_hi [NN * DIN];
__device__ __nv_bfloat16 g_x_lo [NN * DIN];
__device__ __nv_bfloat16 g_xT_hi[DIN * NN];
__device__ __nv_bfloat16 g_xT_lo[DIN * NN];
__device__ __nv_bfloat16 g_WsT_hi[DOUT * DIN];
__device__ __nv_bfloat16 g_WsT_lo[DOUT * DIN];
__device__ __nv_bfloat16 g_WnT_hi[DOUT * DIN];
__device__ __nv_bfloat16 g_WnT_lo[DOUT * DIN];
__device__ __nv_bfloat16 g_WcT_hi[DOUT * 2 * DOUT];
__device__ __nv_bfloat16 g_WcT_lo[DOUT * 2 * DOUT];
__device__ __nv_bfloat16 g_agg_hi[NN * DIN];
__device__ __nv_bfloat16 g_agg_lo[NN * DIN];
__device__ __nv_bfloat16 g_cmb_hi[NN * 2 * DOUT];
__device__ __nv_bfloat16 g_cmb_lo[NN * 2 * DOUT];

// ---------------------------------------------------------------------------
// Helpers (base sm_90 features only — NO 'a'-suffix instructions)
// ---------------------------------------------------------------------------
__device__ __forceinline__ uint32_t smem_u32(const void* p) {
    uint32_t a;
    asm("{ .reg .u64 t; cvta.to.shared.u64 t, %1; cvt.u32.u64 %0, t; }"
        : "=r"(a) : "l"(p));
    return a;
}

__device__ __forceinline__ void cp_async16(uint32_t dst, const void* src) {
    asm volatile("cp.async.cg.shared.global [%0], [%1], 16;"
                 :: "r"(dst), "l"(src) : "memory");
}
__device__ __forceinline__ void cp_commit() {
    asm volatile("cp.async.commit_group;" ::: "memory");
}
template <int N>
__device__ __forceinline__ void cp_wait() {
    asm volatile("cp.async.wait_group %0;" :: "n"(N) : "memory");
}

__device__ __forceinline__ void sts64(uint32_t addr, uint2 v) {
    asm volatile("st.shared.v2.b32 [%0], {%1,%2};"
                 :: "r"(addr), "r"(v.x), "r"(v.y) : "memory");
}

__device__ __forceinline__ void ldmx4(uint32_t* r, uint32_t a) {
    asm volatile("ldmatrix.sync.aligned.m8n8.x4.shared.b16 {%0,%1,%2,%3}, [%4];"
                 : "=r"(r[0]), "=r"(r[1]), "=r"(r[2]), "=r"(r[3]) : "r"(a));
}

// D += A * B, m16n8k16, bf16 in, fp32 accum
__device__ __forceinline__ void mma_bf16(float* c, const uint32_t* a, const uint32_t* b) {
    asm volatile(
        "mma.sync.aligned.m16n8k16.row.col.f32.bf16.bf16.f32 "
        "{%0,%1,%2,%3}, {%4,%5,%6,%7}, {%8,%9}, {%0,%1,%2,%3};"
        : "+f"(c[0]), "+f"(c[1]), "+f"(c[2]), "+f"(c[3])
        : "r"(a[0]), "r"(a[1]), "r"(a[2]), "r"(a[3]), "r"(b[0]), "r"(b[1]));
}

#define SW128(o) ((uint32_t)(o) ^ ((((uint32_t)(o)) >> 3) & 0x70u))

// ---------------------------------------------------------------------------
// Prep: transpose + hi/lo bf16 split.
// sel 0: x -> g_x_* and g_xT_*; sel 1: W_self -> g_WsT_*; sel 2: W_nb; sel 3: W_comb
// ---------------------------------------------------------------------------
__global__ void transpose_split_kernel(const float* __restrict__ src, int R, int C, int sel) {
    __shared__ float t[32][33];
    int tx = threadIdx.x, ty = threadIdx.y;
    int r = blockIdx.y * 32 + ty;
    int c = blockIdx.x * 32 + tx;
    float v = src[(size_t)r * C + c];

    __nv_bfloat16 *dh = nullptr, *dl = nullptr, *th, *tl;
    if (sel == 0)      { dh = g_x_hi;  dl = g_x_lo;  th = g_xT_hi;  tl = g_xT_lo; }
    else if (sel == 1) { th = g_WsT_hi; tl = g_WsT_lo; }
    else if (sel == 2) { th = g_WnT_hi; tl = g_WnT_lo; }
    else               { th = g_WcT_hi; tl = g_WcT_lo; }

    if (dh) {
        __nv_bfloat16 h = __float2bfloat16(v);
        dh[(size_t)r * C + c] = h;
        dl[(size_t)r * C + c] = __float2bfloat16(v - __bfloat162float(h));
    }
    t[ty][tx] = v;
    __syncthreads();
    float v2 = t[tx][ty];                 // = src[by*32+tx][bx*32+ty]
    int rr = blockIdx.y * 32 + tx;
    int cc = blockIdx.x * 32 + ty;
    __nv_bfloat16 h2 = __float2bfloat16(v2);
    th[(size_t)cc * R + rr] = h2;
    tl[(size_t)cc * R + rr] = __float2bfloat16(v2 - __bfloat162float(h2));
}

// ---------------------------------------------------------------------------
// GEMM1: agg = (mask @ (x_hi + x_lo)) / max(deg,1)
// CTA tile 128x128, K-chunk 64, 8 warps (2x4), warp tile 64x32.
// A (mask) via LDG+convert+STS; B (xT hi/lo) via cp.async. 2-stage pipeline.
// SMEM stage: A 16KB | Bh 16KB | Bl 16KB = 48KB.  2 stages + 2KB header.
// ---------------------------------------------------------------------------
#define G1_STAGE 49152
#define G1_SMEM  (2048 + 2 * G1_STAGE)
#define G1_NIT   128

__global__ void __launch_bounds__(256, 1) gemm1_kernel(const int* __restrict__ adj) {
    extern __shared__ char smem[];
    int* s_deg = (int*)smem;
    uint32_t sb = (smem_u32(smem) + 1024 + 1023) & ~1023u;

    int tid = threadIdx.x, wid = tid >> 5, lid = tid & 31;
    int wm = wid >> 2, wn = wid & 3;
    int m0 = blockIdx.y << 7;
    int n0 = blockIdx.x << 7;

    if (tid < 128) s_deg[tid] = 0;
    __syncthreads();

    const int4* adj4 = (const int4*)adj;
    int cnt[8] = {0, 0, 0, 0, 0, 0, 0, 0};

    auto load_a = [&](int s, int it) {
        uint32_t base = sb + s * G1_STAGE;
        int k0 = it << 6;
#pragma unroll
        for (int j = 0; j < 8; ++j) {
            int idx = tid + (j << 8);
            int row = idx >> 4, c4 = idx & 15;     // 16 int4 (64 ints) per row
            int4 a = __ldg(&adj4[(size_t)(m0 + row) * 2048 + (k0 >> 2) + c4]);
            cnt[j] += (a.x != 0) + (a.y != 0) + (a.z != 0) + (a.w != 0);
            uint2 p;
            p.x = ((a.x != 0) ? 0x3F80u : 0u) | (((a.y != 0) ? 0x3F80u : 0u) << 16);
            p.y = ((a.z != 0) ? 0x3F80u : 0u) | (((a.w != 0) ? 0x3F80u : 0u) << 16);
            sts64(base + SW128(row * 128 + c4 * 8), p);
        }
    };

    auto load_b = [&](int s, int it) {
        uint32_t bh = sb + s * G1_STAGE + 16384;
        uint32_t bl = bh + 16384;
        int k0 = it << 6;
#pragma unroll
        for (int j = 0; j < 4; ++j) {
            int idx = tid + (j << 8);
            int row = idx >> 3, c16 = idx & 7;     // 8 x 16B per row
            size_t gi = (size_t)(n0 + row) * NN + k0 + c16 * 8;
            uint32_t so = SW128(row * 128 + c16 * 16);
            cp_async16(bh + so, g_xT_hi + gi);
            cp_async16(bl + so, g_xT_lo + gi);
        }
    };

    float c[4][4][4];
#pragma unroll
    for (int mi = 0; mi < 4; ++mi)
#pragma unroll
        for (int ni = 0; ni < 4; ++ni)
#pragma unroll
            for (int q = 0; q < 4; ++q) c[mi][ni][q] = 0.0f;

    load_a(0, 0); load_b(0, 0); cp_commit();

#pragma unroll 1
    for (int it = 0; it < G1_NIT; ++it) {
        int s = it & 1;
        if (it + 1 < G1_NIT) {
            load_a(s ^ 1, it + 1); load_b(s ^ 1, it + 1); cp_commit();
            cp_wait<1>();
        } else {
            cp_wait<0>();
        }
        __syncthreads();

        uint32_t abase = sb + s * G1_STAGE;
        uint32_t bhbase = abase + 16384;
        uint32_t blbase = abase + 32768;
#pragma unroll
        for (int k16 = 0; k16 < 4; ++k16) {
            uint32_t a[4][4];
#pragma unroll
            for (int mi = 0; mi < 4; ++mi) {
                int row = wm * 64 + mi * 16 + (lid & 7) + ((lid >> 3) & 1) * 8;
                ldmx4(a[mi], abase + SW128(row * 128 + k16 * 32 + ((lid >> 4) & 1) * 16));
            }
            uint32_t bhf[2][4], blf[2][4];
#pragma unroll
            for (int np = 0; np < 2; ++np) {
                int row = wn * 32 + np * 16 + (lid & 7) + (lid >> 4) * 8;
                uint32_t off = SW128(row * 128 + k16 * 32 + ((lid >> 3) & 1) * 16);
                ldmx4(bhf[np], bhbase + off);
                ldmx4(blf[np], blbase + off);
            }
#pragma unroll
            for (int mi = 0; mi < 4; ++mi)
#pragma unroll
                for (int ni = 0; ni < 4; ++ni) {
                    mma_bf16(c[mi][ni], a[mi], &bhf[ni >> 1][(ni & 1) * 2]);
                    mma_bf16(c[mi][ni], a[mi], &blf[ni >> 1][(ni & 1) * 2]);
                }
        }
        __syncthreads();
    }

#pragma unroll
    for (int j = 0; j < 8; ++j)
        atomicAdd(&s_deg[(tid + (j << 8)) >> 4], cnt[j]);
    __syncthreads();

#pragma unroll
    for (int mi = 0; mi < 4; ++mi) {
        int r0 = wm * 64 + mi * 16 + (lid >> 2);
        int r1 = r0 + 8;
        float inv0 = 1.0f / fmaxf((float)s_deg[r0], 1.0f);
        float inv1 = 1.0f / fmaxf((float)s_deg[r1], 1.0f);
#pragma unroll
        for (int ni = 0; ni < 4; ++ni) {
            int col = n0 + wn * 32 + ni * 8 + (lid & 3) * 2;
            float v0 = c[mi][ni][0] * inv0, v1 = c[mi][ni][1] * inv0;
            float v2 = c[mi][ni][2] * inv1, v3 = c[mi][ni][3] * inv1;
            __nv_bfloat16 h0 = __float2bfloat16(v0), h1 = __float2bfloat16(v1);
            __nv_bfloat16 h2 = __float2bfloat16(v2), h3 = __float2bfloat16(v3);
            size_t o0 = (size_t)(m0 + r0) * DIN + col;
            size_t o1 = (size_t)(m0 + r1) * DIN + col;
            *(__nv_bfloat162*)&g_agg_hi[o0] = {h0, h1};
            *(__nv_bfloat162*)&g_agg_hi[o1] = {h2, h3};
            __nv_bfloat16 l0 = __float2bfloat16(v0 - __bfloat162float(h0));
            __nv_bfloat16 l1 = __float2bfloat16(v1 - __bfloat162float(h1));
            __nv_bfloat16 l2 = __float2bfloat16(v2 - __bfloat162float(h2));
            __nv_bfloat16 l3 = __float2bfloat16(v3 - __bfloat162float(h3));
            *(__nv_bfloat162*)&g_agg_lo[o0] = {l0, l1};
            *(__nv_bfloat162*)&g_agg_lo[o1] = {l2, l3};
        }
    }
}

// ---------------------------------------------------------------------------
// Dense GEMM, 3-term split: D = Ah*Bh + Al*Bh + Ah*Bl  (+bias, optional relu)
// sel 0: x @ Ws -> cmb[:,0:512]; sel 1: agg @ Wn -> cmb[:,512:1024];
// sel 2: cmb @ Wc -> relu -> out (fp32)
// SMEM stage: Ah 16K | Al 16K | Bh 16K | Bl 16K = 64KB, 2 stages.
// ---------------------------------------------------------------------------
#define GD_STAGE 65536
#define GD_SMEM  (2048 + 2 * GD_STAGE)

__global__ void __launch_bounds__(256, 1) gemm_dense_kernel(int sel,
                                                            const float* __restrict__ bias,
                                                            float* __restrict__ outf) {
    extern __shared__ char smem[];
    uint32_t sb = (smem_u32(smem) + 1024 + 1023) & ~1023u;

    int tid = threadIdx.x, wid = tid >> 5, lid = tid & 31;
    int wm = wid >> 2, wn = wid & 3;
    int m0 = blockIdx.y << 7;
    int n0 = blockIdx.x << 7;

    const __nv_bfloat16 *Ah, *Al, *Bh, *Bl;
    int K, coff = 0;
    bool relu = false;
    if (sel == 0)      { Ah = g_x_hi;   Al = g_x_lo;   Bh = g_WsT_hi; Bl = g_WsT_lo; K = 512; }
    else if (sel == 1) { Ah = g_agg_hi; Al = g_agg_lo; Bh = g_WnT_hi; Bl = g_WnT_lo; K = 512; coff = 512; }
    else               { Ah = g_cmb_hi; Al = g_cmb_lo; Bh = g_WcT_hi; Bl = g_WcT_lo; K = 1024; relu = true; }
    const int NIT = K >> 6;

    auto load_stage = [&](int s, int it) {
        uint32_t ah = sb + s * GD_STAGE;
        uint32_t al = ah + 16384;
        uint32_t bh = ah + 32768;
        uint32_t bl = ah + 49152;
        int k0 = it << 6;
#pragma unroll
        for (int j = 0; j < 4; ++j) {
            int idx = tid + (j << 8);
            int row = idx >> 3, c16 = idx & 7;
            uint32_t so = SW128(row * 128 + c16 * 16);
            size_t ga = (size_t)(m0 + row) * K + k0 + c16 * 8;
            size_t gb = (size_t)(n0 + row) * K + k0 + c16 * 8;
            cp_async16(ah + so, Ah + ga);
            cp_async16(al + so, Al + ga);
            cp_async16(bh + so, Bh + gb);
            cp_async16(bl + so, Bl + gb);
        }
    };

    float c[4][4][4];
#pragma unroll
    for (int mi = 0; mi < 4; ++mi)
#pragma unroll
        for (int ni = 0; ni < 4; ++ni)
#pragma unroll
            for (int q = 0; q < 4; ++q) c[mi][ni][q] = 0.0f;

    load_stage(0, 0); cp_commit();

#pragma unroll 1
    for (int it = 0; it < NIT; ++it) {
        int s = it & 1;
        if (it + 1 < NIT) {
            load_stage(s ^ 1, it + 1); cp_commit();
            cp_wait<1>();
        } else {
            cp_wait<0>();
        }
        __syncthreads();

        uint32_t ahb = sb + s * GD_STAGE;
        uint32_t alb = ahb + 16384;
        uint32_t bhb = ahb + 32768;
        uint32_t blb = ahb + 49152;
#pragma unroll
        for (int k16 = 0; k16 < 4; ++k16) {
            uint32_t ah[4][4], al[4][4];
#pragma unroll
            for (int mi = 0; mi < 4; ++mi) {
                int row = wm * 64 + mi * 16 + (lid & 7) + ((lid >> 3) & 1) * 8;
                uint32_t off = SW128(row * 128 + k16 * 32 + ((lid >> 4) & 1) * 16);
                ldmx4(ah[mi], ahb + off);
                ldmx4(al[mi], alb + off);
            }
            uint32_t bhf[2][4], blf[2][4];
#pragma unroll
            for (int np = 0; np < 2; ++np) {
                int row = wn * 32 + np * 16 + (lid & 7) + (lid >> 4) * 8;
                uint32_t off = SW128(row * 128 + k16 * 32 + ((lid >> 3) & 1) * 16);
                ldmx4(bhf[np], bhb + off);
                ldmx4(blf[np], blb + off);
            }
#pragma unroll
            for (int mi = 0; mi < 4; ++mi)
#pragma unroll
                for (int ni = 0; ni < 4; ++ni) {
                    const uint32_t* bh2 = &bhf[ni >> 1][(ni & 1) * 2];
                    const uint32_t* bl2 = &blf[ni >> 1][(ni & 1) * 2];
                    mma_bf16(c[mi][ni], ah[mi], bh2);
                    mma_bf16(c[mi][ni], al[mi], bh2);
                    mma_bf16(c[mi][ni], ah[mi], bl2);
                }
        }
        __syncthreads();
    }

#pragma unroll
    for (int mi = 0; mi < 4; ++mi) {
        int r0 = wm * 64 + mi * 16 + (lid >> 2);
        int r1 = r0 + 8;
#pragma unroll
        for (int ni = 0; ni < 4; ++ni) {
            int col = n0 + wn * 32 + ni * 8 + (lid & 3) * 2;
            float b0 = bias[col], b1 = bias[col + 1];
            float v0 = c[mi][ni][0] + b0, v1 = c[mi][ni][1] + b1;
            float v2 = c[mi][ni][2] + b0, v3 = c[mi][ni][3] + b1;
            if (relu) {
                size_t o0 = (size_t)(m0 + r0) * DOUT + col;
                size_t o1 = (size_t)(m0 + r1) * DOUT + col;
                outf[o0]     = fmaxf(v0, 0.0f);
                outf[o0 + 1] = fmaxf(v1, 0.0f);
                outf[o1]     = fmaxf(v2, 0.0f);
                outf[o1 + 1] = fmaxf(v3, 0.0f);
            } else {
                __nv_bfloat16 h0 = __float2bfloat16(v0), h1 = __float2bfloat16(v1);
                __nv_bfloat16 h2 = __float2bfloat16(v2), h3 = __float2bfloat16(v3);
                size_t o0 = (size_t)(m0 + r0) * 1024 + coff + col;
                size_t o1 = (size_t)(m0 + r1) * 1024 + coff + col;
                *(__nv_bfloat162*)&g_cmb_hi[o0] = {h0, h1};
                *(__nv_bfloat162*)&g_cmb_hi[o1] = {h2, h3};
                __nv_bfloat16 l0 = __float2bfloat16(v0 - __bfloat162float(h0));
                __nv_bfloat16 l1 = __float2bfloat16(v1 - __bfloat162float(h1));
                __nv_bfloat16 l2 = __float2bfloat16(v2 - __bfloat162float(h2));
                __nv_bfloat16 l3 = __float2bfloat16(v3 - __bfloat162float(h3));
                *(__nv_bfloat162*)&g_cmb_lo[o0] = {l0, l1};
                *(__nv_bfloat162*)&g_cmb_lo[o1] = {l2, l3};
            }
        }
    }
}

// ---------------------------------------------------------------------------
// Launch
// ---------------------------------------------------------------------------
extern "C" void kernel_launch(void* const* d_in, const int* in_sizes, int n_in,
                              void* d_out, int out_size) {
    const float* x   = (const float*)d_in[0];
    const int*   adj = (const int*)d_in[1];
    const float* Ws  = (const float*)d_in[2];
    const float* bs  = (const float*)d_in[3];
    const float* Wn  = (const float*)d_in[4];
    const float* bn  = (const float*)d_in[5];
    const float* Wc  = (const float*)d_in[6];
    const float* bc  = (const float*)d_in[7];
    float* out = (float*)d_out;

    cudaFuncSetAttribute(gemm1_kernel, cudaFuncAttributeMaxDynamicSharedMemorySize, G1_SMEM);
    cudaFuncSetAttribute(gemm_dense_kernel, cudaFuncAttributeMaxDynamicSharedMemorySize, GD_SMEM);

    dim3 tb(32, 32);
    transpose_split_kernel<<<dim3(16, 256), tb>>>(x,  NN,   DIN, 0);
    transpose_split_kernel<<<dim3(16, 16),  tb>>>(Ws, DIN,  DOUT, 1);
    transpose_split_kernel<<<dim3(16, 16),  tb>>>(Wn, DIN,  DOUT, 2);
    transpose_split_kernel<<<dim3(16, 32),  tb>>>(Wc, 2 * DOUT, DOUT, 3);

    // blockIdx.x = N-block (fast) so the 4 N-blocks of one M-block are
    // co-resident -> adj row-block read from DRAM once, reused in L2.
    gemm1_kernel<<<dim3(4, 64), 256, G1_SMEM>>>(adj);

    gemm_dense_kernel<<<dim3(4, 64), 256, GD_SMEM>>>(0, bs, nullptr);
    gemm_dense_kernel<<<dim3(4, 64), 256, GD_SMEM>>>(1, bn, nullptr);
    gemm_dense_kernel<<<dim3(4, 64), 256, GD_SMEM>>>(2, bc, out);
}

// round 10
// speedup vs baseline: 1.4280x; 1.4280x over previous
#include <cuda_runtime.h>
#include <cuda_fp16.h>
#include <stdint.h>

#define NN   8192
#define DIN  512
#define DOUT 512

// ---------------------------------------------------------------------------
// Device scratch (static __device__ globals; allocation-free rule)
// fp16 single-term everywhere: measured rel_err 8.7e-6 with 2-term bf16
// (mantissa 8+8) -> fp16 (mantissa 11) predicts ~2.6e-4, under the 1e-3 gate.
// ---------------------------------------------------------------------------
__device__ __half g_x  [NN * DIN];        // x row-major (A of sel0)
__device__ __half g_xT [DIN * NN];        // x^T: [n][k] rows for GEMM1 B
__device__ __half g_WsT[DOUT * DIN];
__device__ __half g_WnT[DOUT * DIN];
__device__ __half g_WcT[DOUT * 2 * DOUT];
__device__ __half g_agg[NN * DIN];
__device__ __half g_cmb[NN * 2 * DOUT];

// ---------------------------------------------------------------------------
// Helpers (base sm_90 features only — NO 'a'-suffix instructions)
// ---------------------------------------------------------------------------
__device__ __forceinline__ uint32_t smem_u32(const void* p) {
    uint32_t a;
    asm("{ .reg .u64 t; cvta.to.shared.u64 t, %1; cvt.u32.u64 %0, t; }"
        : "=r"(a) : "l"(p));
    return a;
}

__device__ __forceinline__ void cp_async16(uint32_t dst, const void* src) {
    asm volatile("cp.async.cg.shared.global [%0], [%1], 16;"
                 :: "r"(dst), "l"(src) : "memory");
}
__device__ __forceinline__ void cp_commit() {
    asm volatile("cp.async.commit_group;" ::: "memory");
}
template <int N>
__device__ __forceinline__ void cp_wait() {
    asm volatile("cp.async.wait_group %0;" :: "n"(N) : "memory");
}

__device__ __forceinline__ void sts64(uint32_t addr, uint2 v) {
    asm volatile("st.shared.v2.b32 [%0], {%1,%2};"
                 :: "r"(addr), "r"(v.x), "r"(v.y) : "memory");
}

__device__ __forceinline__ void ldmx4(uint32_t* r, uint32_t a) {
    asm volatile("ldmatrix.sync.aligned.m8n8.x4.shared.b16 {%0,%1,%2,%3}, [%4];"
                 : "=r"(r[0]), "=r"(r[1]), "=r"(r[2]), "=r"(r[3]) : "r"(a));
}

// D += A * B, m16n8k16, fp16 in, fp32 accum
__device__ __forceinline__ void mma_f16(float* c, const uint32_t* a, const uint32_t* b) {
    asm volatile(
        "mma.sync.aligned.m16n8k16.row.col.f32.f16.f16.f32 "
        "{%0,%1,%2,%3}, {%4,%5,%6,%7}, {%8,%9}, {%0,%1,%2,%3};"
        : "+f"(c[0]), "+f"(c[1]), "+f"(c[2]), "+f"(c[3])
        : "r"(a[0]), "r"(a[1]), "r"(a[2]), "r"(a[3]), "r"(b[0]), "r"(b[1]));
}

#define SW128(o) ((uint32_t)(o) ^ ((((uint32_t)(o)) >> 3) & 0x70u))

// ---------------------------------------------------------------------------
// Prep: fp16 convert + transpose.
// sel 0: x -> g_x and g_xT; sel 1: W_self -> g_WsT; sel 2: W_nb; sel 3: W_comb
// ---------------------------------------------------------------------------
__global__ void transpose_half_kernel(const float* __restrict__ src, int R, int C, int sel) {
    __shared__ float t[32][33];
    int tx = threadIdx.x, ty = threadIdx.y;
    int r = blockIdx.y * 32 + ty;
    int c = blockIdx.x * 32 + tx;
    float v = src[(size_t)r * C + c];

    __half *dd = nullptr, *tt;
    if (sel == 0)      { dd = g_x;  tt = g_xT; }
    else if (sel == 1) { tt = g_WsT; }
    else if (sel == 2) { tt = g_WnT; }
    else               { tt = g_WcT; }

    if (dd) dd[(size_t)r * C + c] = __float2half(v);
    t[ty][tx] = v;
    __syncthreads();
    float v2 = t[tx][ty];                 // = src[by*32+tx][bx*32+ty]
    int rr = blockIdx.y * 32 + tx;
    int cc = blockIdx.x * 32 + ty;
    tt[(size_t)cc * R + rr] = __float2half(v2);
}

// ---------------------------------------------------------------------------
// GEMM1: agg = (mask @ x) / max(deg,1)   [single fp16 term]
// CTA tile 128x128, K-chunk 64, 8 warps (2x4), warp tile 64x32.
// A (mask fp16 {0,1}) via LDG+convert+STS; B (xT fp16) via cp.async.
// SMEM stage: A 16KB | B 16KB = 32KB.  2 stages + 2KB header.
// ---------------------------------------------------------------------------
#define G1_STAGE 32768
#define G1_SMEM  (2048 + 2 * G1_STAGE)
#define G1_NIT   128

__global__ void __launch_bounds__(256, 1) gemm1_kernel(const int* __restrict__ adj) {
    extern __shared__ char smem[];
    int* s_deg = (int*)smem;
    uint32_t sb = (smem_u32(smem) + 1024 + 1023) & ~1023u;

    int tid = threadIdx.x, wid = tid >> 5, lid = tid & 31;
    int wm = wid >> 2, wn = wid & 3;
    int m0 = blockIdx.y << 7;
    int n0 = blockIdx.x << 7;

    if (tid < 128) s_deg[tid] = 0;
    __syncthreads();

    const int4* adj4 = (const int4*)adj;
    int cnt[8] = {0, 0, 0, 0, 0, 0, 0, 0};

    auto load_a = [&](int s, int it) {
        uint32_t base = sb + s * G1_STAGE;
        int k0 = it << 6;
#pragma unroll
        for (int j = 0; j < 8; ++j) {
            int idx = tid + (j << 8);
            int row = idx >> 4, c4 = idx & 15;     // 16 int4 (64 ints) per row
            int4 a = __ldg(&adj4[(size_t)(m0 + row) * 2048 + (k0 >> 2) + c4]);
            cnt[j] += (a.x != 0) + (a.y != 0) + (a.z != 0) + (a.w != 0);
            uint2 p;
            p.x = ((a.x != 0) ? 0x3C00u : 0u) | (((a.y != 0) ? 0x3C00u : 0u) << 16);
            p.y = ((a.z != 0) ? 0x3C00u : 0u) | (((a.w != 0) ? 0x3C00u : 0u) << 16);
            sts64(base + SW128(row * 128 + c4 * 8), p);
        }
    };

    auto load_b = [&](int s, int it) {
        uint32_t bb = sb + s * G1_STAGE + 16384;
        int k0 = it << 6;
#pragma unroll
        for (int j = 0; j < 4; ++j) {
            int idx = tid + (j << 8);
            int row = idx >> 3, c16 = idx & 7;     // 8 x 16B per row
            size_t gi = (size_t)(n0 + row) * NN + k0 + c16 * 8;
            cp_async16(bb + SW128(row * 128 + c16 * 16), g_xT + gi);
        }
    };

    float c[4][4][4];
#pragma unroll
    for (int mi = 0; mi < 4; ++mi)
#pragma unroll
        for (int ni = 0; ni < 4; ++ni)
#pragma unroll
            for (int q = 0; q < 4; ++q) c[mi][ni][q] = 0.0f;

    load_a(0, 0); load_b(0, 0); cp_commit();

#pragma unroll 1
    for (int it = 0; it < G1_NIT; ++it) {
        int s = it & 1;
        if (it + 1 < G1_NIT) {
            load_a(s ^ 1, it + 1); load_b(s ^ 1, it + 1); cp_commit();
            cp_wait<1>();
        } else {
            cp_wait<0>();
        }
        __syncthreads();

        uint32_t abase = sb + s * G1_STAGE;
        uint32_t bbase = abase + 16384;
#pragma unroll
        for (int k16 = 0; k16 < 4; ++k16) {
            uint32_t a[4][4];
#pragma unroll
            for (int mi = 0; mi < 4; ++mi) {
                int row = wm * 64 + mi * 16 + (lid & 7) + ((lid >> 3) & 1) * 8;
                ldmx4(a[mi], abase + SW128(row * 128 + k16 * 32 + ((lid >> 4) & 1) * 16));
            }
            uint32_t bf[2][4];
#pragma unroll
            for (int np = 0; np < 2; ++np) {
                int row = wn * 32 + np * 16 + (lid & 7) + (lid >> 4) * 8;
                ldmx4(bf[np], bbase + SW128(row * 128 + k16 * 32 + ((lid >> 3) & 1) * 16));
            }
#pragma unroll
            for (int mi = 0; mi < 4; ++mi)
#pragma unroll
                for (int ni = 0; ni < 4; ++ni)
                    mma_f16(c[mi][ni], a[mi], &bf[ni >> 1][(ni & 1) * 2]);
        }
        __syncthreads();
    }

#pragma unroll
    for (int j = 0; j < 8; ++j)
        atomicAdd(&s_deg[(tid + (j << 8)) >> 4], cnt[j]);
    __syncthreads();

#pragma unroll
    for (int mi = 0; mi < 4; ++mi) {
        int r0 = wm * 64 + mi * 16 + (lid >> 2);
        int r1 = r0 + 8;
        float inv0 = 1.0f / fmaxf((float)s_deg[r0], 1.0f);
        float inv1 = 1.0f / fmaxf((float)s_deg[r1], 1.0f);
#pragma unroll
        for (int ni = 0; ni < 4; ++ni) {
            int col = n0 + wn * 32 + ni * 8 + (lid & 3) * 2;
            size_t o0 = (size_t)(m0 + r0) * DIN + col;
            size_t o1 = (size_t)(m0 + r1) * DIN + col;
            __half2 h0 = __floats2half2_rn(c[mi][ni][0] * inv0, c[mi][ni][1] * inv0);
            __half2 h1 = __floats2half2_rn(c[mi][ni][2] * inv1, c[mi][ni][3] * inv1);
            *(__half2*)&g_agg[o0] = h0;
            *(__half2*)&g_agg[o1] = h1;
        }
    }
}

// ---------------------------------------------------------------------------
// Dense GEMM, single fp16 term: D = A*B (+bias, optional relu)
// sel 0: x @ Ws -> cmb[:,0:512]; sel 1: agg @ Wn -> cmb[:,512:1024];
// sel 2: cmb @ Wc -> relu -> out (fp32)
// SMEM stage: A 16K | B 16K = 32KB, 2 stages.
// ---------------------------------------------------------------------------
#define GD_STAGE 32768
#define GD_SMEM  (2048 + 2 * GD_STAGE)

__global__ void __launch_bounds__(256, 1) gemm_dense_kernel(int sel,
                                                            const float* __restrict__ bias,
                                                            float* __restrict__ outf) {
    extern __shared__ char smem[];
    uint32_t sb = (smem_u32(smem) + 1024 + 1023) & ~1023u;

    int tid = threadIdx.x, wid = tid >> 5, lid = tid & 31;
    int wm = wid >> 2, wn = wid & 3;
    int m0 = blockIdx.y << 7;
    int n0 = blockIdx.x << 7;

    const __half *A, *B;
    int K, coff = 0;
    bool relu = false;
    if (sel == 0)      { A = g_x;   B = g_WsT; K = 512; }
    else if (sel == 1) { A = g_agg; B = g_WnT; K = 512; coff = 512; }
    else               { A = g_cmb; B = g_WcT; K = 1024; relu = true; }
    const int NIT = K >> 6;

    auto load_stage = [&](int s, int it) {
        uint32_t ab = sb + s * GD_STAGE;
        uint32_t bb = ab + 16384;
        int k0 = it << 6;
#pragma unroll
        for (int j = 0; j < 4; ++j) {
            int idx = tid + (j << 8);
            int row = idx >> 3, c16 = idx & 7;
            uint32_t so = SW128(row * 128 + c16 * 16);
            size_t ga = (size_t)(m0 + row) * K + k0 + c16 * 8;
            size_t gb = (size_t)(n0 + row) * K + k0 + c16 * 8;
            cp_async16(ab + so, A + ga);
            cp_async16(bb + so, B + gb);
        }
    };

    float c[4][4][4];
#pragma unroll
    for (int mi = 0; mi < 4; ++mi)
#pragma unroll
        for (int ni = 0; ni < 4; ++ni)
#pragma unroll
            for (int q = 0; q < 4; ++q) c[mi][ni][q] = 0.0f;

    load_stage(0, 0); cp_commit();

#pragma unroll 1
    for (int it = 0; it < NIT; ++it) {
        int s = it & 1;
        if (it + 1 < NIT) {
            load_stage(s ^ 1, it + 1); cp_commit();
            cp_wait<1>();
        } else {
            cp_wait<0>();
        }
        __syncthreads();

        uint32_t ab = sb + s * GD_STAGE;
        uint32_t bb = ab + 16384;
#pragma unroll
        for (int k16 = 0; k16 < 4; ++k16) {
            uint32_t a[4][4];
#pragma unroll
            for (int mi = 0; mi < 4; ++mi) {
                int row = wm * 64 + mi * 16 + (lid & 7) + ((lid >> 3) & 1) * 8;
                ldmx4(a[mi], ab + SW128(row * 128 + k16 * 32 + ((lid >> 4) & 1) * 16));
            }
            uint32_t bf[2][4];
#pragma unroll
            for (int np = 0; np < 2; ++np) {
                int row = wn * 32 + np * 16 + (lid & 7) + (lid >> 4) * 8;
                ldmx4(bf[np], bb + SW128(row * 128 + k16 * 32 + ((lid >> 3) & 1) * 16));
            }
#pragma unroll
            for (int mi = 0; mi < 4; ++mi)
#pragma unroll
                for (int ni = 0; ni < 4; ++ni)
                    mma_f16(c[mi][ni], a[mi], &bf[ni >> 1][(ni & 1) * 2]);
        }
        __syncthreads();
    }

#pragma unroll
    for (int mi = 0; mi < 4; ++mi) {
        int r0 = wm * 64 + mi * 16 + (lid >> 2);
        int r1 = r0 + 8;
#pragma unroll
        for (int ni = 0; ni < 4; ++ni) {
            int col = n0 + wn * 32 + ni * 8 + (lid & 3) * 2;
            float b0 = bias[col], b1 = bias[col + 1];
            float v0 = c[mi][ni][0] + b0, v1 = c[mi][ni][1] + b1;
            float v2 = c[mi][ni][2] + b0, v3 = c[mi][ni][3] + b1;
            if (relu) {
                size_t o0 = (size_t)(m0 + r0) * DOUT + col;
                size_t o1 = (size_t)(m0 + r1) * DOUT + col;
                outf[o0]     = fmaxf(v0, 0.0f);
                outf[o0 + 1] = fmaxf(v1, 0.0f);
                outf[o1]     = fmaxf(v2, 0.0f);
                outf[o1 + 1] = fmaxf(v3, 0.0f);
            } else {
                size_t o0 = (size_t)(m0 + r0) * 1024 + coff + col;
                size_t o1 = (size_t)(m0 + r1) * 1024 + coff + col;
                *(__half2*)&g_cmb[o0] = __floats2half2_rn(v0, v1);
                *(__half2*)&g_cmb[o1] = __floats2half2_rn(v2, v3);
            }
        }
    }
}

// ---------------------------------------------------------------------------
// Launch
// ---------------------------------------------------------------------------
extern "C" void kernel_launch(void* const* d_in, const int* in_sizes, int n_in,
                              void* d_out, int out_size) {
    const float* x   = (const float*)d_in[0];
    const int*   adj = (const int*)d_in[1];
    const float* Ws  = (const float*)d_in[2];
    const float* bs  = (const float*)d_in[3];
    const float* Wn  = (const float*)d_in[4];
    const float* bn  = (const float*)d_in[5];
    const float* Wc  = (const float*)d_in[6];
    const float* bc  = (const float*)d_in[7];
    float* out = (float*)d_out;

    cudaFuncSetAttribute(gemm1_kernel, cudaFuncAttributeMaxDynamicSharedMemorySize, G1_SMEM);
    cudaFuncSetAttribute(gemm_dense_kernel, cudaFuncAttributeMaxDynamicSharedMemorySize, GD_SMEM);

    dim3 tb(32, 32);
    transpose_half_kernel<<<dim3(16, 256), tb>>>(x,  NN,   DIN, 0);
    transpose_half_kernel<<<dim3(16, 16),  tb>>>(Ws, DIN,  DOUT, 1);
    transpose_half_kernel<<<dim3(16, 16),  tb>>>(Wn, DIN,  DOUT, 2);
    transpose_half_kernel<<<dim3(16, 32),  tb>>>(Wc, 2 * DOUT, DOUT, 3);

    // blockIdx.x = N-block (fast) so the 4 N-blocks of one M-block are
    // co-resident -> adj row-block read from DRAM once, reused in L2.
    gemm1_kernel<<<dim3(4, 64), 256, G1_SMEM>>>(adj);

    gemm_dense_kernel<<<dim3(4, 64), 256, GD_SMEM>>>(0, bs, nullptr);
    gemm_dense_kernel<<<dim3(4, 64), 256, GD_SMEM>>>(1, bn, nullptr);
    gemm_dense_kernel<<<dim3(4, 64), 256, GD_SMEM>>>(2, bc, out);
}

// round 11
// speedup vs baseline: 1.4986x; 1.0495x over previous
#include <cuda_runtime.h>
#include <cuda_fp16.h>
#include <stdint.h>

#define NN   8192
#define DIN  512
#define DOUT 512

// ---------------------------------------------------------------------------
// Device scratch (static __device__ globals; allocation-free rule)
// ---------------------------------------------------------------------------
__device__ __half g_x  [NN * DIN];        // x row-major (A of sel0)
__device__ __half g_xT [DIN * NN];        // x^T: [n][k] rows for GEMM1 B
__device__ __half g_WsT[DOUT * DIN];
__device__ __half g_WnT[DOUT * DIN];
__device__ __half g_WcT[DOUT * 2 * DOUT];
__device__ __half g_agg[NN * DIN];
__device__ __half g_cmb[NN * 2 * DOUT];

// ---------------------------------------------------------------------------
// Helpers (base sm_90 features only — NO 'a'-suffix instructions)
// ---------------------------------------------------------------------------
__device__ __forceinline__ uint32_t smem_u32(const void* p) {
    uint32_t a;
    asm("{ .reg .u64 t; cvta.to.shared.u64 t, %1; cvt.u32.u64 %0, t; }"
        : "=r"(a) : "l"(p));
    return a;
}

__device__ __forceinline__ void cp_async16(uint32_t dst, const void* src) {
    asm volatile("cp.async.cg.shared.global [%0], [%1], 16;"
                 :: "r"(dst), "l"(src) : "memory");
}
__device__ __forceinline__ void cp_commit() {
    asm volatile("cp.async.commit_group;" ::: "memory");
}
template <int N>
__device__ __forceinline__ void cp_wait() {
    asm volatile("cp.async.wait_group %0;" :: "n"(N) : "memory");
}

__device__ __forceinline__ void sts64(uint32_t addr, uint2 v) {
    asm volatile("st.shared.v2.b32 [%0], {%1,%2};"
                 :: "r"(addr), "r"(v.x), "r"(v.y) : "memory");
}

__device__ __forceinline__ void ldmx4(uint32_t* r, uint32_t a) {
    asm volatile("ldmatrix.sync.aligned.m8n8.x4.shared.b16 {%0,%1,%2,%3}, [%4];"
                 : "=r"(r[0]), "=r"(r[1]), "=r"(r[2]), "=r"(r[3]) : "r"(a));
}

// D += A * B, m16n8k16, fp16 in, fp32 accum
__device__ __forceinline__ void mma_f16(float* c, const uint32_t* a, const uint32_t* b) {
    asm volatile(
        "mma.sync.aligned.m16n8k16.row.col.f32.f16.f16.f32 "
        "{%0,%1,%2,%3}, {%4,%5,%6,%7}, {%8,%9}, {%0,%1,%2,%3};"
        : "+f"(c[0]), "+f"(c[1]), "+f"(c[2]), "+f"(c[3])
        : "r"(a[0]), "r"(a[1]), "r"(a[2]), "r"(a[3]), "r"(b[0]), "r"(b[1]));
}

#define SW128(o) ((uint32_t)(o) ^ ((((uint32_t)(o)) >> 3) & 0x70u))

// ---------------------------------------------------------------------------
// Prep: fp16 convert + transpose.
// sel 0: x -> g_x and g_xT; sel 1: W_self -> g_WsT; sel 2: W_nb; sel 3: W_comb
// ---------------------------------------------------------------------------
__global__ void transpose_half_kernel(const float* __restrict__ src, int R, int C, int sel) {
    __shared__ float t[32][33];
    int tx = threadIdx.x, ty = threadIdx.y;
    int r = blockIdx.y * 32 + ty;
    int c = blockIdx.x * 32 + tx;
    float v = src[(size_t)r * C + c];

    __half *dd = nullptr, *tt;
    if (sel == 0)      { dd = g_x;  tt = g_xT; }
    else if (sel == 1) { tt = g_WsT; }
    else if (sel == 2) { tt = g_WnT; }
    else               { tt = g_WcT; }

    if (dd) dd[(size_t)r * C + c] = __float2half(v);
    t[ty][tx] = v;
    __syncthreads();
    float v2 = t[tx][ty];                 // = src[by*32+tx][bx*32+ty]
    int rr = blockIdx.y * 32 + tx;
    int cc = blockIdx.x * 32 + ty;
    tt[(size_t)cc * R + rr] = __float2half(v2);
}

// ---------------------------------------------------------------------------
// GEMM1: agg = (mask @ x) / max(deg,1)   [fp16, 3-stage pipeline, 1 sync/iter]
// CTA tile 128x128, K-chunk 64, 8 warps (2x4), warp tile 64x32.
// A (mask fp16 {0,1}) via LDG->cvt->regs->STS(bottom); B (xT) via cp.async.
// SMEM: 3 stages x (A 16KB | B 16KB) = 96KB + 2KB header.
// ---------------------------------------------------------------------------
#define G1_STAGE 32768
#define G1_SMEM  (2048 + 3 * G1_STAGE)
#define G1_NIT   128

__global__ void __launch_bounds__(256, 1) gemm1_kernel(const int* __restrict__ adj) {
    extern __shared__ char smem[];
    int* s_deg = (int*)smem;
    uint32_t sb = (smem_u32(smem) + 1024 + 1023) & ~1023u;

    int tid = threadIdx.x, wid = tid >> 5, lid = tid & 31;
    int wm = wid >> 2, wn = wid & 3;
    int m0 = blockIdx.y << 7;
    int n0 = blockIdx.x << 7;

    if (tid < 128) s_deg[tid] = 0;

    const int4* adj4 = (const int4*)adj;
    int cnt[8] = {0, 0, 0, 0, 0, 0, 0, 0};

    // A: LDG 128x64 ints -> fp16 pairs in regs (16 regs), count nonzeros
    auto load_a_regs = [&](int it, uint2* pa) {
        int k0 = it << 6;
#pragma unroll
        for (int j = 0; j < 8; ++j) {
            int idx = tid + (j << 8);
            int row = idx >> 4, c4 = idx & 15;     // 16 int4 (64 ints) per row
            int4 a = __ldg(&adj4[(size_t)(m0 + row) * 2048 + (k0 >> 2) + c4]);
            cnt[j] += (a.x != 0) + (a.y != 0) + (a.z != 0) + (a.w != 0);
            pa[j].x = ((a.x != 0) ? 0x3C00u : 0u) | (((a.y != 0) ? 0x3C00u : 0u) << 16);
            pa[j].y = ((a.z != 0) ? 0x3C00u : 0u) | (((a.w != 0) ? 0x3C00u : 0u) << 16);
        }
    };
    auto store_a = [&](int s, const uint2* pa) {
        uint32_t base = sb + s * G1_STAGE;
#pragma unroll
        for (int j = 0; j < 8; ++j) {
            int idx = tid + (j << 8);
            int row = idx >> 4, c4 = idx & 15;
            sts64(base + SW128(row * 128 + c4 * 8), pa[j]);
        }
    };
    auto load_b = [&](int s, int it) {
        uint32_t bb = sb + s * G1_STAGE + 16384;
        int k0 = it << 6;
#pragma unroll
        for (int j = 0; j < 4; ++j) {
            int idx = tid + (j << 8);
            int row = idx >> 3, c16 = idx & 7;     // 8 x 16B per row
            size_t gi = (size_t)(n0 + row) * NN + k0 + c16 * 8;
            cp_async16(bb + SW128(row * 128 + c16 * 16), g_xT + gi);
        }
    };

    float c[4][4][4];
#pragma unroll
    for (int mi = 0; mi < 4; ++mi)
#pragma unroll
        for (int ni = 0; ni < 4; ++ni)
#pragma unroll
            for (int q = 0; q < 4; ++q) c[mi][ni][q] = 0.0f;

    // Prologue: fill stages 0 and 1
    {
        uint2 pa[8];
        load_a_regs(0, pa); load_b(0, 0); store_a(0, pa); cp_commit();
        load_a_regs(1, pa); load_b(1, 1); store_a(1, pa); cp_commit();
    }

    int s = 0, s2 = 2;   // s = it%3 (consume), s2 = (it+2)%3 (produce)
#pragma unroll 1
    for (int it = 0; it < G1_NIT; ++it) {
        cp_wait<1>();
        __syncthreads();   // stage s ready for all; stage s2 (= it-1's) free

        bool pre = (it + 2) < G1_NIT;
        uint2 pa[8];
        if (pre) { load_a_regs(it + 2, pa); load_b(s2, it + 2); }

        uint32_t abase = sb + s * G1_STAGE;
        uint32_t bbase = abase + 16384;
#pragma unroll
        for (int k16 = 0; k16 < 4; ++k16) {
            uint32_t a[4][4];
#pragma unroll
            for (int mi = 0; mi < 4; ++mi) {
                int row = wm * 64 + mi * 16 + (lid & 7) + ((lid >> 3) & 1) * 8;
                ldmx4(a[mi], abase + SW128(row * 128 + k16 * 32 + ((lid >> 4) & 1) * 16));
            }
            uint32_t bf[2][4];
#pragma unroll
            for (int np = 0; np < 2; ++np) {
                int row = wn * 32 + np * 16 + (lid & 7) + (lid >> 4) * 8;
                ldmx4(bf[np], bbase + SW128(row * 128 + k16 * 32 + ((lid >> 3) & 1) * 16));
            }
#pragma unroll
            for (int mi = 0; mi < 4; ++mi)
#pragma unroll
                for (int ni = 0; ni < 4; ++ni)
                    mma_f16(c[mi][ni], a[mi], &bf[ni >> 1][(ni & 1) * 2]);
        }

        if (pre) store_a(s2, pa);
        cp_commit();

        s = (s == 2) ? 0 : s + 1;
        s2 = (s2 == 2) ? 0 : s2 + 1;
    }

#pragma unroll
    for (int j = 0; j < 8; ++j)
        atomicAdd(&s_deg[(tid + (j << 8)) >> 4], cnt[j]);
    __syncthreads();

#pragma unroll
    for (int mi = 0; mi < 4; ++mi) {
        int r0 = wm * 64 + mi * 16 + (lid >> 2);
        int r1 = r0 + 8;
        float inv0 = 1.0f / fmaxf((float)s_deg[r0], 1.0f);
        float inv1 = 1.0f / fmaxf((float)s_deg[r1], 1.0f);
#pragma unroll
        for (int ni = 0; ni < 4; ++ni) {
            int col = n0 + wn * 32 + ni * 8 + (lid & 3) * 2;
            size_t o0 = (size_t)(m0 + r0) * DIN + col;
            size_t o1 = (size_t)(m0 + r1) * DIN + col;
            *(__half2*)&g_agg[o0] = __floats2half2_rn(c[mi][ni][0] * inv0, c[mi][ni][1] * inv0);
            *(__half2*)&g_agg[o1] = __floats2half2_rn(c[mi][ni][2] * inv1, c[mi][ni][3] * inv1);
        }
    }
}

// ---------------------------------------------------------------------------
// Dense GEMM, fp16, 3-stage pipeline, 1 sync/iter: D = A*B (+bias, opt relu)
// sel 0: x @ Ws -> cmb[:,0:512]; sel 1: agg @ Wn -> cmb[:,512:1024];
// sel 2: cmb @ Wc -> relu -> out (fp32)
// SMEM: 3 stages x (A 16K | B 16K) = 96KB.
// ---------------------------------------------------------------------------
#define GD_STAGE 32768
#define GD_SMEM  (2048 + 3 * GD_STAGE)

__global__ void __launch_bounds__(256, 1) gemm_dense_kernel(int sel,
                                                            const float* __restrict__ bias,
                                                            float* __restrict__ outf) {
    extern __shared__ char smem[];
    uint32_t sb = (smem_u32(smem) + 1024 + 1023) & ~1023u;

    int tid = threadIdx.x, wid = tid >> 5, lid = tid & 31;
    int wm = wid >> 2, wn = wid & 3;
    int m0 = blockIdx.y << 7;
    int n0 = blockIdx.x << 7;

    const __half *A, *B;
    int K, coff = 0;
    bool relu = false;
    if (sel == 0)      { A = g_x;   B = g_WsT; K = 512; }
    else if (sel == 1) { A = g_agg; B = g_WnT; K = 512; coff = 512; }
    else               { A = g_cmb; B = g_WcT; K = 1024; relu = true; }
    const int NIT = K >> 6;

    auto load_stage = [&](int s, int it) {
        uint32_t ab = sb + s * GD_STAGE;
        uint32_t bb = ab + 16384;
        int k0 = it << 6;
#pragma unroll
        for (int j = 0; j < 4; ++j) {
            int idx = tid + (j << 8);
            int row = idx >> 3, c16 = idx & 7;
            uint32_t so = SW128(row * 128 + c16 * 16);
            size_t ga = (size_t)(m0 + row) * K + k0 + c16 * 8;
            size_t gb = (size_t)(n0 + row) * K + k0 + c16 * 8;
            cp_async16(ab + so, A + ga);
            cp_async16(bb + so, B + gb);
        }
    };

    float c[4][4][4];
#pragma unroll
    for (int mi = 0; mi < 4; ++mi)
#pragma unroll
        for (int ni = 0; ni < 4; ++ni)
#pragma unroll
            for (int q = 0; q < 4; ++q) c[mi][ni][q] = 0.0f;

    load_stage(0, 0); cp_commit();
    load_stage(1, 1); cp_commit();

    int s = 0, s2 = 2;
#pragma unroll 1
    for (int it = 0; it < NIT; ++it) {
        cp_wait<1>();
        __syncthreads();

        if (it + 2 < NIT) load_stage(s2, it + 2);

        uint32_t ab = sb + s * GD_STAGE;
        uint32_t bb = ab + 16384;
#pragma unroll
        for (int k16 = 0; k16 < 4; ++k16) {
            uint32_t a[4][4];
#pragma unroll
            for (int mi = 0; mi < 4; ++mi) {
                int row = wm * 64 + mi * 16 + (lid & 7) + ((lid >> 3) & 1) * 8;
                ldmx4(a[mi], ab + SW128(row * 128 + k16 * 32 + ((lid >> 4) & 1) * 16));
            }
            uint32_t bf[2][4];
#pragma unroll
            for (int np = 0; np < 2; ++np) {
                int row = wn * 32 + np * 16 + (lid & 7) + (lid >> 4) * 8;
                ldmx4(bf[np], bb + SW128(row * 128 + k16 * 32 + ((lid >> 3) & 1) * 16));
            }
#pragma unroll
            for (int mi = 0; mi < 4; ++mi)
#pragma unroll
                for (int ni = 0; ni < 4; ++ni)
                    mma_f16(c[mi][ni], a[mi], &bf[ni >> 1][(ni & 1) * 2]);
        }
        cp_commit();

        s = (s == 2) ? 0 : s + 1;
        s2 = (s2 == 2) ? 0 : s2 + 1;
    }

#pragma unroll
    for (int mi = 0; mi < 4; ++mi) {
        int r0 = wm * 64 + mi * 16 + (lid >> 2);
        int r1 = r0 + 8;
#pragma unroll
        for (int ni = 0; ni < 4; ++ni) {
            int col = n0 + wn * 32 + ni * 8 + (lid & 3) * 2;
            float b0 = __ldg(&bias[col]), b1 = __ldg(&bias[col + 1]);
            float v0 = c[mi][ni][0] + b0, v1 = c[mi][ni][1] + b1;
            float v2 = c[mi][ni][2] + b0, v3 = c[mi][ni][3] + b1;
            if (relu) {
                size_t o0 = (size_t)(m0 + r0) * DOUT + col;
                size_t o1 = (size_t)(m0 + r1) * DOUT + col;
                outf[o0]     = fmaxf(v0, 0.0f);
                outf[o0 + 1] = fmaxf(v1, 0.0f);
                outf[o1]     = fmaxf(v2, 0.0f);
                outf[o1 + 1] = fmaxf(v3, 0.0f);
            } else {
                size_t o0 = (size_t)(m0 + r0) * 1024 + coff + col;
                size_t o1 = (size_t)(m0 + r1) * 1024 + coff + col;
                *(__half2*)&g_cmb[o0] = __floats2half2_rn(v0, v1);
                *(__half2*)&g_cmb[o1] = __floats2half2_rn(v2, v3);
            }
        }
    }
}

// ---------------------------------------------------------------------------
// Launch
// ---------------------------------------------------------------------------
extern "C" void kernel_launch(void* const* d_in, const int* in_sizes, int n_in,
                              void* d_out, int out_size) {
    const float* x   = (const float*)d_in[0];
    const int*   adj = (const int*)d_in[1];
    const float* Ws  = (const float*)d_in[2];
    const float* bs  = (const float*)d_in[3];
    const float* Wn  = (const float*)d_in[4];
    const float* bn  = (const float*)d_in[5];
    const float* Wc  = (const float*)d_in[6];
    const float* bc  = (const float*)d_in[7];
    float* out = (float*)d_out;

    cudaFuncSetAttribute(gemm1_kernel, cudaFuncAttributeMaxDynamicSharedMemorySize, G1_SMEM);
    cudaFuncSetAttribute(gemm_dense_kernel, cudaFuncAttributeMaxDynamicSharedMemorySize, GD_SMEM);

    dim3 tb(32, 32);
    transpose_half_kernel<<<dim3(16, 256), tb>>>(x,  NN,   DIN, 0);
    transpose_half_kernel<<<dim3(16, 16),  tb>>>(Ws, DIN,  DOUT, 1);
    transpose_half_kernel<<<dim3(16, 16),  tb>>>(Wn, DIN,  DOUT, 2);
    transpose_half_kernel<<<dim3(16, 32),  tb>>>(Wc, 2 * DOUT, DOUT, 3);

    // blockIdx.x = N-block (fast) so the 4 N-blocks of one M-block are
    // co-resident -> adj row-block read from DRAM once, reused in L2.
    gemm1_kernel<<<dim3(4, 64), 256, G1_SMEM>>>(adj);

    gemm_dense_kernel<<<dim3(4, 64), 256, GD_SMEM>>>(0, bs, nullptr);
    gemm_dense_kernel<<<dim3(4, 64), 256, GD_SMEM>>>(1, bn, nullptr);
    gemm_dense_kernel<<<dim3(4, 64), 256, GD_SMEM>>>(2, bc, out);
}